// round 1
// baseline (speedup 1.0000x reference)
#include <cuda_runtime.h>

// PAU (rational activation): out = P(z)/Q(z), z = x + center
//   P(z) = a0 + a1 z + ... + a5 z^5  (Horner)
//   Q(z) = 1 + |z|*(|b1| + |z|*(|b2| + |z|*(|b3| + |z|*|b4|)))
// Inputs (metadata order): x [16,2048,4096] f32, center [1] f32,
//                          numerator [6] f32, denominator [4] f32.
// Memory-bound: 1 GiB total traffic.

__device__ __forceinline__ float pau_one(float x, float c,
                                         const float a[6], const float b[4]) {
    float z = x + c;
    // numerator Horner
    float p = a[5];
    p = fmaf(p, z, a[4]);
    p = fmaf(p, z, a[3]);
    p = fmaf(p, z, a[2]);
    p = fmaf(p, z, a[1]);
    p = fmaf(p, z, a[0]);
    // denominator Horner on |z| with |b|
    float az = fabsf(z);
    float q = b[3];
    q = fmaf(q, az, b[2]);
    q = fmaf(q, az, b[1]);
    q = fmaf(q, az, b[0]);
    q = fmaf(q, az, 1.0f);
    return p / q;
}

__global__ void pau_kernel(const float* __restrict__ x,
                           const float* __restrict__ center,
                           const float* __restrict__ numerator,
                           const float* __restrict__ denominator,
                           float* __restrict__ out,
                           long long n4, long long n) {
    // Load params (cheap, L1/L2-cached broadcasts)
    float c = __ldg(center);
    float a[6];
#pragma unroll
    for (int i = 0; i < 6; i++) a[i] = __ldg(numerator + i);
    float b[4];
#pragma unroll
    for (int i = 0; i < 4; i++) b[i] = fabsf(__ldg(denominator + i));

    long long tid = (long long)blockIdx.x * blockDim.x + threadIdx.x;
    long long stride = (long long)gridDim.x * blockDim.x;

    const float4* x4 = (const float4*)x;
    float4* o4 = (float4*)out;

    for (long long i = tid; i < n4; i += stride) {
        float4 v = x4[i];
        float4 r;
        r.x = pau_one(v.x, c, a, b);
        r.y = pau_one(v.y, c, a, b);
        r.z = pau_one(v.z, c, a, b);
        r.w = pau_one(v.w, c, a, b);
        o4[i] = r;
    }
    // scalar tail (n % 4 != 0 safety; no-op for this shape)
    for (long long i = n4 * 4 + tid; i < n; i += stride) {
        out[i] = pau_one(x[i], c, a, b);
    }
}

extern "C" void kernel_launch(void* const* d_in, const int* in_sizes, int n_in,
                              void* d_out, int out_size) {
    const float* x = (const float*)d_in[0];
    const float* center = (const float*)d_in[1];
    const float* numerator = (const float*)d_in[2];
    const float* denominator = (const float*)d_in[3];
    float* out = (float*)d_out;

    long long n = (long long)in_sizes[0];
    long long n4 = n / 4;

    const int threads = 256;
    // Enough blocks to saturate 148 SMs with deep occupancy while keeping
    // a grid-stride loop of a few iterations per thread (MLP from unroll).
    long long want = (n4 + threads - 1) / threads;
    int blocks = (int)((want < 148LL * 2048LL) ? want : 148LL * 2048LL);
    if (blocks < 1) blocks = 1;

    pau_kernel<<<blocks, threads>>>(x, center, numerator, denominator, out, n4, n);
}

// round 2
// speedup vs baseline: 1.4783x; 1.4783x over previous
#include <cuda_runtime.h>

// PAU rational activation: out = P(z)/Q(z), z = x + center.
// x: [16,2048,4096] f32 (N = 134217728), center[1], numerator[6], denominator[4].
// Strictly HBM-bound: 1 GiB traffic. Target ~8TB/s streaming.

// Params in constant memory: [0]=center, [1..6]=a0..a5, [7..10]=b0..b3
__constant__ float c_params[11];

__device__ __forceinline__ float pau_one(float x) {
    const float c = c_params[0];
    float z = x + c;
    // numerator Horner (coeffs as c[bank] operands in FFMA)
    float p = c_params[6];
    p = fmaf(p, z, c_params[5]);
    p = fmaf(p, z, c_params[4]);
    p = fmaf(p, z, c_params[3]);
    p = fmaf(p, z, c_params[2]);
    p = fmaf(p, z, c_params[1]);
    // denominator Horner on |z| with |b| (|.| folds into FFMA src modifiers)
    float az = fabsf(z);
    float q = fabsf(c_params[10]);
    q = fmaf(q, az, fabsf(c_params[9]));
    q = fmaf(q, az, fabsf(c_params[8]));
    q = fmaf(q, az, fabsf(c_params[7]));
    q = fmaf(q, az, 1.0f);
    // fast division: MUFU.RCP + FMUL, err ~2^-21 << 1e-3 tolerance
    return __fdividef(p, q);
}

__device__ __forceinline__ float4 pau_vec(float4 v) {
    float4 r;
    r.x = pau_one(v.x);
    r.y = pau_one(v.y);
    r.z = pau_one(v.z);
    r.w = pau_one(v.w);
    return r;
}

// Main kernel: 256 threads/block, each thread does 4 float4 (16 elems),
// loads front-batched (MLP=4), coalesced at block granularity.
// Block covers 1024 consecutive float4s.
__global__ void __launch_bounds__(256) pau_kernel16(
    const float4* __restrict__ x4, float4* __restrict__ o4) {
    unsigned base = blockIdx.x * 1024u + threadIdx.x;
    // front-batch all 4 independent loads
    float4 v0 = x4[base];
    float4 v1 = x4[base + 256u];
    float4 v2 = x4[base + 512u];
    float4 v3 = x4[base + 768u];
    o4[base]        = pau_vec(v0);
    o4[base + 256u] = pau_vec(v1);
    o4[base + 512u] = pau_vec(v2);
    o4[base + 768u] = pau_vec(v3);
}

// Generic tail kernel for any leftover elements (unused for this shape).
__global__ void pau_tail(const float* __restrict__ x, float* __restrict__ out,
                         long long start, long long n) {
    long long i = start + (long long)blockIdx.x * blockDim.x + threadIdx.x;
    if (i < n) out[i] = pau_one(x[i]);
}

extern "C" void kernel_launch(void* const* d_in, const int* in_sizes, int n_in,
                              void* d_out, int out_size) {
    const float* x = (const float*)d_in[0];
    const float* center = (const float*)d_in[1];
    const float* numerator = (const float*)d_in[2];
    const float* denominator = (const float*)d_in[3];
    float* out = (float*)d_out;

    long long n = (long long)in_sizes[0];

    // Fill constant params (async D2D copies; graph-capturable memcpy nodes)
    cudaMemcpyToSymbolAsync(c_params, center, sizeof(float), 0,
                            cudaMemcpyDeviceToDevice);
    cudaMemcpyToSymbolAsync(c_params, numerator, 6 * sizeof(float),
                            1 * sizeof(float), cudaMemcpyDeviceToDevice);
    cudaMemcpyToSymbolAsync(c_params, denominator, 4 * sizeof(float),
                            7 * sizeof(float), cudaMemcpyDeviceToDevice);

    // Main: blocks of 1024 float4 = 4096 elements each
    long long n4 = n / 4;
    long long nblocks = n4 / 1024;          // full blocks
    long long covered = nblocks * 4096;     // elements covered by main kernel

    if (nblocks > 0) {
        pau_kernel16<<<(unsigned)nblocks, 256>>>((const float4*)x, (float4*)out);
    }
    if (covered < n) {
        long long rem = n - covered;
        int tb = (int)((rem + 255) / 256);
        pau_tail<<<tb, 256>>>(x, out, covered, n);
    }
}

// round 3
// speedup vs baseline: 1.5234x; 1.0305x over previous
#include <cuda_runtime.h>

// PAU rational activation: out = P(z)/Q(z), z = x + center.
// x: [16,2048,4096] f32 (N = 134217728), center[1], numerator[6], denominator[4].
// Strictly HBM-bound: 1 GiB traffic. Single-node graph, streaming cache hints.

struct PauParams {
    float c;
    float a0, a1, a2, a3, a4, a5;
    float b0, b1, b2, b3;   // already |.|'d at load time
};

__device__ __forceinline__ float pau_one(float x, const PauParams& P) {
    float z = x + P.c;
    float p = P.a5;
    p = fmaf(p, z, P.a4);
    p = fmaf(p, z, P.a3);
    p = fmaf(p, z, P.a2);
    p = fmaf(p, z, P.a1);
    p = fmaf(p, z, P.a0);
    float az = fabsf(z);
    float q = P.b3;
    q = fmaf(q, az, P.b2);
    q = fmaf(q, az, P.b1);
    q = fmaf(q, az, P.b0);
    q = fmaf(q, az, 1.0f);
    // fast division: MUFU.RCP + FMUL, err ~2^-21 << 1e-3 tolerance
    return __fdividef(p, q);
}

__device__ __forceinline__ float4 pau_vec(float4 v, const PauParams& P) {
    float4 r;
    r.x = pau_one(v.x, P);
    r.y = pau_one(v.y, P);
    r.z = pau_one(v.z, P);
    r.w = pau_one(v.w, P);
    return r;
}

__device__ __forceinline__ PauParams load_params(
    const float* __restrict__ center,
    const float* __restrict__ num,
    const float* __restrict__ den) {
    PauParams P;
    P.c  = __ldg(center);
    P.a0 = __ldg(num + 0); P.a1 = __ldg(num + 1); P.a2 = __ldg(num + 2);
    P.a3 = __ldg(num + 3); P.a4 = __ldg(num + 4); P.a5 = __ldg(num + 5);
    P.b0 = fabsf(__ldg(den + 0)); P.b1 = fabsf(__ldg(den + 1));
    P.b2 = fabsf(__ldg(den + 2)); P.b3 = fabsf(__ldg(den + 3));
    return P;
}

// Main kernel: 256 threads/block, each thread processes 4 float4 (16 elems).
// Front-batched streaming loads (MLP=4), evict-first cache policy.
__global__ void __launch_bounds__(256) pau_kernel16(
    const float4* __restrict__ x4, float4* __restrict__ o4,
    const float* __restrict__ center,
    const float* __restrict__ num,
    const float* __restrict__ den) {
    const PauParams P = load_params(center, num, den);

    unsigned base = blockIdx.x * 1024u + threadIdx.x;
    float4 v0 = __ldcs(x4 + base);
    float4 v1 = __ldcs(x4 + base + 256u);
    float4 v2 = __ldcs(x4 + base + 512u);
    float4 v3 = __ldcs(x4 + base + 768u);
    __stcs(o4 + base,        pau_vec(v0, P));
    __stcs(o4 + base + 256u, pau_vec(v1, P));
    __stcs(o4 + base + 512u, pau_vec(v2, P));
    __stcs(o4 + base + 768u, pau_vec(v3, P));
}

// Generic tail kernel for leftover elements (unused for this exact shape).
__global__ void pau_tail(const float* __restrict__ x, float* __restrict__ out,
                         const float* __restrict__ center,
                         const float* __restrict__ num,
                         const float* __restrict__ den,
                         long long start, long long n) {
    const PauParams P = load_params(center, num, den);
    long long i = start + (long long)blockIdx.x * blockDim.x + threadIdx.x;
    if (i < n) out[i] = pau_one(x[i], P);
}

extern "C" void kernel_launch(void* const* d_in, const int* in_sizes, int n_in,
                              void* d_out, int out_size) {
    const float* x = (const float*)d_in[0];
    const float* center = (const float*)d_in[1];
    const float* numerator = (const float*)d_in[2];
    const float* denominator = (const float*)d_in[3];
    float* out = (float*)d_out;

    long long n = (long long)in_sizes[0];
    long long n4 = n / 4;
    long long nblocks = n4 / 1024;       // each block covers 4096 elements
    long long covered = nblocks * 4096;

    if (nblocks > 0) {
        pau_kernel16<<<(unsigned)nblocks, 256>>>(
            (const float4*)x, (float4*)out, center, numerator, denominator);
    }
    if (covered < n) {
        long long rem = n - covered;
        int tb = (int)((rem + 255) / 256);
        pau_tail<<<tb, 256>>>(x, out, center, numerator, denominator, covered, n);
    }
}